// round 10
// baseline (speedup 1.0000x reference)
#include <cuda_runtime.h>
#include <cuda_fp16.h>
#include <cstdint>
#include <math.h>

#define B_SZ 2
#define S_LEN 2048
#define D_MODEL 2048
#define NH 16
#define NKVH 4
#define HD 128
#define MROWS (B_SZ*S_LEN)

// fp16 scratch (allocation-free rule: __device__ globals)
__device__ __half g_Xh[(size_t)MROWS*D_MODEL];
__device__ __half g_Wqkv[(size_t)3072*D_MODEL];     // wq(2048) | wk(512) | wv(512) rows
__device__ __half g_Woh[(size_t)D_MODEL*D_MODEL];
__device__ __half g_Qh[(size_t)B_SZ*NH*S_LEN*HD];   // [b,h,s,d] post-rope
__device__ __half g_Kh[(size_t)B_SZ*NKVH*S_LEN*HD];
__device__ __half g_Vh[(size_t)B_SZ*NKVH*S_LEN*HD];
__device__ __half g_Oh[(size_t)B_SZ*S_LEN*D_MODEL]; // [b,s,h*d]

__device__ __forceinline__ void mma_f16(float* c, const uint4& a, const uint2& b){
    asm volatile("mma.sync.aligned.m16n8k16.row.col.f32.f16.f16.f32 "
        "{%0,%1,%2,%3}, {%4,%5,%6,%7}, {%8,%9}, {%0,%1,%2,%3};"
        : "+f"(c[0]), "+f"(c[1]), "+f"(c[2]), "+f"(c[3])
        : "r"(a.x), "r"(a.y), "r"(a.z), "r"(a.w), "r"(b.x), "r"(b.y));
}
#define LDSM4(v, addr) asm volatile( \
    "ldmatrix.sync.aligned.m8n8.x4.shared.b16 {%0,%1,%2,%3}, [%4];" \
    : "=r"((v).x), "=r"((v).y), "=r"((v).z), "=r"((v).w) : "r"(addr))
#define LDSM4T(v, addr) asm volatile( \
    "ldmatrix.sync.aligned.m8n8.x4.trans.shared.b16 {%0,%1,%2,%3}, [%4];" \
    : "=r"((v).x), "=r"((v).y), "=r"((v).z), "=r"((v).w) : "r"(addr))
#define CP16(dst, src) asm volatile( \
    "cp.async.cg.shared.global [%0], [%1], 16;" :: "r"(dst), "l"(src))
#define CPCOMMIT asm volatile("cp.async.commit_group;")
#define CPWAIT(n) asm volatile("cp.async.wait_group %0;" :: "n"(n))

// ---------------- single-launch fp32 -> fp16 conversion prepass ----------------
// segments (float4 units): x 2097152 | wq 1048576 | wk 262144 | wv 262144 | wo 1048576
#define CVT_TOTAL4 4718592
__global__ void cvt_all(const float* __restrict__ x,  const float* __restrict__ wq,
                        const float* __restrict__ wk, const float* __restrict__ wv,
                        const float* __restrict__ wo)
{
    int i = blockIdx.x*256 + threadIdx.x;
    const float* s; __half* d; int off;
    if (i < 2097152)      { s = x;  d = g_Xh;                          off = i; }
    else if (i < 3145728) { s = wq; d = g_Wqkv;                        off = i - 2097152; }
    else if (i < 3407872) { s = wk; d = g_Wqkv + (size_t)2048*D_MODEL; off = i - 3145728; }
    else if (i < 3670016) { s = wv; d = g_Wqkv + (size_t)2560*D_MODEL; off = i - 3407872; }
    else                  { s = wo; d = g_Woh;                         off = i - 3670016; }
    float4 f = ((const float4*)s)[off];
    ((__half2*)d)[2*off]   = __floats2half2_rn(f.x, f.y);
    ((__half2*)d)[2*off+1] = __floats2half2_rn(f.z, f.w);
}

// ============ GEMM: C = A * W^T (fp16 in, cp.async + ldmatrix) ============
// BM=128, BN=256, BK=64, 3 stages, 256 threads (8 warps 2x4, 64x64 each).
// MODE 0: C f32 row-major [M,2048].  MODE 3: fused QKV -> fp16 [b,h,s,d] + rope.
#define GEMM_SMEM (3*(16384+32768))

template<int MODE>
__global__ void __launch_bounds__(256) gemm_h(
    const __half* __restrict__ A, const __half* __restrict__ Bw,
    float* __restrict__ Cf,
    const float* __restrict__ fcos, const float* __restrict__ fsin)
{
    extern __shared__ char sm[];
    const uint32_t sb = (uint32_t)__cvta_generic_to_shared(sm);
    const int tid = threadIdx.x, lane = tid & 31, wid = tid >> 5;
    const int wm = wid & 1, wn = wid >> 1;          // 2 x 4 warps
    const int m0 = blockIdx.y * 128;
    const int n0g = blockIdx.x * 256;

    __half* Ch = nullptr; int n0 = n0g, Hn = 0, rope = 0;
    if (MODE == 3) {
        if (n0g < 2048)      { Ch = g_Qh; n0 = n0g;        Hn = NH;   rope = 1; }
        else if (n0g < 2560) { Ch = g_Kh; n0 = n0g - 2048; Hn = NKVH; rope = 1; }
        else                 { Ch = g_Vh; n0 = n0g - 2560; Hn = NKVH; rope = 0; }
    }
    const __half* Ag0 = A  + (size_t)m0  * D_MODEL;
    const __half* Bg0 = Bw + (size_t)n0g * D_MODEL;

    auto loadStage = [&](int s, int kc){
        uint32_t ab = sb + s*16384;
        uint32_t bb = sb + 49152 + s*32768;
        const __half* Ag = Ag0 + kc;
        const __half* Bg = Bg0 + kc;
        #pragma unroll
        for (int i = 0; i < 4; i++){           // A: 128x64 fp16 = 1024 x 16B
            int idx = tid + 256*i;
            int r = idx >> 3, c = idx & 7;
            CP16(ab + r*128 + ((c ^ (r & 7)) << 4), Ag + (size_t)r*D_MODEL + c*8);
        }
        #pragma unroll
        for (int i = 0; i < 8; i++){           // B: 256x64 fp16 = 2048 x 16B
            int idx = tid + 256*i;
            int r = idx >> 3, c = idx & 7;
            CP16(bb + r*128 + ((c ^ (r & 7)) << 4), Bg + (size_t)r*D_MODEL + c*8);
        }
        CPCOMMIT;
    };

    float acc[4][8][4];
    #pragma unroll
    for (int mt = 0; mt < 4; mt++)
        #pragma unroll
        for (int n = 0; n < 8; n++)
            #pragma unroll
            for (int r = 0; r < 4; r++) acc[mt][n][r] = 0.f;

    loadStage(0, 0);
    loadStage(1, 64);

    for (int i = 0; i < 32; i++){
        if (i < 31) { CPWAIT(1); } else { CPWAIT(0); }
        __syncthreads();
        if (i + 2 < 32) loadStage((i+2)%3, (i+2)*64);

        const uint32_t ab = sb + (i%3)*16384;
        const uint32_t bb = sb + 49152 + (i%3)*32768;
        #pragma unroll
        for (int kt = 0; kt < 4; kt++){
            uint4 af[4];
            #pragma unroll
            for (int mt = 0; mt < 4; mt++){
                int r = wm*64 + mt*16 + (lane & 15);
                int c = kt*2 + (lane >> 4);
                LDSM4(af[mt], ab + r*128 + ((c ^ (r & 7)) << 4));
            }
            #pragma unroll
            for (int p = 0; p < 4; p++){
                int r = wn*64 + p*16 + ((lane >> 4) << 3) + (lane & 7);
                int c = kt*2 + ((lane >> 3) & 1);
                uint4 bq;
                LDSM4(bq, bb + r*128 + ((c ^ (r & 7)) << 4));
                uint2 b0 = make_uint2(bq.x, bq.y);
                uint2 b1 = make_uint2(bq.z, bq.w);
                #pragma unroll
                for (int mt = 0; mt < 4; mt++){
                    mma_f16(acc[mt][2*p],   af[mt], b0);
                    mma_f16(acc[mt][2*p+1], af[mt], b1);
                }
            }
        }
    }

    // -------- epilogue --------
    const int l4 = lane >> 2;
    const int l2 = (lane & 3) * 2;
    #pragma unroll
    for (int mt = 0; mt < 4; mt++){
        #pragma unroll
        for (int n = 0; n < 8; n++){
            const int col = (MODE == 0 ? n0g : n0) + wn*64 + n*8 + l2;
            #pragma unroll
            for (int half = 0; half < 2; half++){
                const int row = m0 + wm*64 + mt*16 + l4 + half*8;
                float xr = acc[mt][n][half*2 + 0];
                float xi = acc[mt][n][half*2 + 1];
                if (MODE == 0){
                    float2 o; o.x = xr; o.y = xi;
                    *(float2*)(Cf + (size_t)row*D_MODEL + col) = o;
                } else {
                    const int b = row >> 11;
                    const int s = row & (S_LEN-1);
                    const int h = col >> 7;
                    const int d = col & (HD-1);
                    __half* op = Ch + (((size_t)(b*Hn + h))*S_LEN + s)*HD + d;
                    if (rope){
                        float cs = fcos[s*(HD/2) + (d>>1)];
                        float sn = fsin[s*(HD/2) + (d>>1)];
                        *(__half2*)op = __floats2half2_rn(xr*cs - xi*sn, xr*sn + xi*cs);
                    } else {
                        *(__half2*)op = __floats2half2_rn(xr, xi);
                    }
                }
            }
        }
    }
}

// ===== Flash attention v2: fp16, BQ=128, BKT=64, cp.async dbuf, ldmatrix =====
// smem: Q 32KB | K[2] 2x16KB | V[2] 2x16KB | P 16KB  = 112KB
#define ATT_SMEM 114688

__global__ void __launch_bounds__(256) attn2()
{
    extern __shared__ char sm[];
    const uint32_t sb = (uint32_t)__cvta_generic_to_shared(sm);
    const uint32_t Qb = sb;
    const uint32_t Kb0 = sb + 32768, Kb1 = sb + 49152;
    const uint32_t Vb0 = sb + 65536, Vb1 = sb + 81920;
    uint32_t* Ps = (uint32_t*)(sm + 98304);   // [8 mt][4 kt][128] words

    const int tid = threadIdx.x, lane = tid & 31, wid = tid >> 5;
    const int bz  = blockIdx.y >> 4;
    const int hh  = blockIdx.y & 15;
    const int kvh = hh >> 2;
    const int qt  = blockIdx.x;
    const int q0  = qt * 128;

    const __half* Qg = g_Qh + ((size_t)(bz*NH   + hh )*S_LEN + q0)*HD;
    const __half* Kg = g_Kh + ((size_t)(bz*NKVH + kvh)*S_LEN)*HD;
    const __half* Vg = g_Vh + ((size_t)(bz*NKVH + kvh)*S_LEN)*HD;

    auto loadKV = [&](int buf, int k0){
        uint32_t kb = buf ? Kb1 : Kb0;
        uint32_t vb = buf ? Vb1 : Vb0;
        #pragma unroll
        for (int i = 0; i < 4; i++){
            int idx = tid + 256*i;
            int r = idx >> 4, c = idx & 15;
            uint32_t off = r*256 + ((c ^ (r & 7)) << 4);
            CP16(kb + off, Kg + (size_t)(k0 + r)*HD + c*8);
            CP16(vb + off, Vg + (size_t)(k0 + r)*HD + c*8);
        }
        CPCOMMIT;
    };

    // group 0: Q + KV(0)
    #pragma unroll
    for (int i = 0; i < 8; i++){
        int idx = tid + 256*i;
        int r = idx >> 4, c = idx & 15;
        CP16(Qb + r*256 + ((c ^ (r & 7)) << 4), Qg + (size_t)r*HD + c*8);
    }
    loadKV(0, 0);

    const int nkt = 2*qt + 2;
    const float scale = 0.08838834764831845f;   // 1/sqrt(128)
    const int qlo = q0 + wid*16 + (lane >> 2);
    const int qhi = qlo + 8;
    const int diagTile = 2*qt + (wid >= 4 ? 1 : 0);

    uint4 qf[8];
    float m0 = -1e30f, m1 = -1e30f, l0 = 0.f, l1 = 0.f;
    float o[16][4];
    #pragma unroll
    for (int nt = 0; nt < 16; nt++)
        #pragma unroll
        for (int r = 0; r < 4; r++) o[nt][r] = 0.f;

    for (int tile = 0; tile < nkt; tile++){
        if (tile + 1 < nkt) { loadKV((tile+1) & 1, (tile+1)*64); CPWAIT(1); }
        else                { CPWAIT(0); }
        __syncthreads();

        if (tile == 0){
            #pragma unroll
            for (int kt = 0; kt < 8; kt++){
                int r = wid*16 + (lane & 15);
                int c = kt*2 + (lane >> 4);
                LDSM4(qf[kt], Qb + r*256 + ((c ^ (r & 7)) << 4));
            }
        }

        const int k0 = tile * 64;
        const bool skip = (tile == 2*qt + 1) && (wid < 4);
        if (!skip){
            const uint32_t kb = (tile & 1) ? Kb1 : Kb0;
            const uint32_t vb = (tile & 1) ? Vb1 : Vb0;

            // ---- S = Q K^T (16 x 64 per warp) ----
            float sacc[8][4];
            #pragma unroll
            for (int n = 0; n < 8; n++)
                #pragma unroll
                for (int r = 0; r < 4; r++) sacc[n][r] = 0.f;
            #pragma unroll
            for (int kt = 0; kt < 8; kt++){
                #pragma unroll
                for (int p = 0; p < 4; p++){
                    int r = p*16 + ((lane >> 4) << 3) + (lane & 7);
                    int c = kt*2 + ((lane >> 3) & 1);
                    uint4 bq;
                    LDSM4(bq, kb + r*256 + ((c ^ (r & 7)) << 4));
                    mma_f16(sacc[2*p],   qf[kt], make_uint2(bq.x, bq.y));
                    mma_f16(sacc[2*p+1], qf[kt], make_uint2(bq.z, bq.w));
                }
            }

            // ---- online softmax ----
            const bool diag = (tile == diagTile);
            float mx0 = -1e30f, mx1 = -1e30f;
            #pragma unroll
            for (int n = 0; n < 8; n++){
                float v0 = sacc[n][0]*scale, v1 = sacc[n][1]*scale;
                float v2 = sacc[n][2]*scale, v3 = sacc[n][3]*scale;
                if (diag){
                    int c0 = k0 + n*8 + (lane & 3)*2;
                    if (c0     > qlo) v0 = -1e30f;
                    if (c0 + 1 > qlo) v1 = -1e30f;
                    if (c0     > qhi) v2 = -1e30f;
                    if (c0 + 1 > qhi) v3 = -1e30f;
                }
                sacc[n][0]=v0; sacc[n][1]=v1; sacc[n][2]=v2; sacc[n][3]=v3;
                mx0 = fmaxf(mx0, fmaxf(v0, v1));
                mx1 = fmaxf(mx1, fmaxf(v2, v3));
            }
            mx0 = fmaxf(mx0, __shfl_xor_sync(0xffffffffu, mx0, 1));
            mx0 = fmaxf(mx0, __shfl_xor_sync(0xffffffffu, mx0, 2));
            mx1 = fmaxf(mx1, __shfl_xor_sync(0xffffffffu, mx1, 1));
            mx1 = fmaxf(mx1, __shfl_xor_sync(0xffffffffu, mx1, 2));
            float nm0 = fmaxf(m0, mx0), nm1 = fmaxf(m1, mx1);
            float cr0 = __expf(m0 - nm0), cr1 = __expf(m1 - nm1);
            m0 = nm0; m1 = nm1;

            float s0 = 0.f, s1 = 0.f;
            #pragma unroll
            for (int n = 0; n < 8; n++){
                float p0 = __expf(sacc[n][0] - nm0);
                float p1 = __expf(sacc[n][1] - nm0);
                float p2 = __expf(sacc[n][2] - nm1);
                float p3 = __expf(sacc[n][3] - nm1);
                s0 += p0 + p1; s1 += p2 + p3;
                __half2 w0 = __floats2half2_rn(p0, p1);
                __half2 w1 = __floats2half2_rn(p2, p3);
                uint2 w; w.x = *(uint32_t*)&w0; w.y = *(uint32_t*)&w1;
                *(uint2*)(Ps + (wid*4 + (n>>1))*128 + (lane>>2)*16 + (lane&3)*4 + 2*(n&1)) = w;
            }
            s0 += __shfl_xor_sync(0xffffffffu, s0, 1);
            s0 += __shfl_xor_sync(0xffffffffu, s0, 2);
            s1 += __shfl_xor_sync(0xffffffffu, s1, 1);
            s1 += __shfl_xor_sync(0xffffffffu, s1, 2);
            l0 = l0*cr0 + s0;
            l1 = l1*cr1 + s1;
            #pragma unroll
            for (int nt = 0; nt < 16; nt++){
                o[nt][0] *= cr0; o[nt][1] *= cr0;
                o[nt][2] *= cr1; o[nt][3] *= cr1;
            }
            __syncwarp();

            // ---- O += P V (16 x 128 per warp) ----
            #pragma unroll
            for (int kt = 0; kt < 4; kt++){
                uint4 pf = *(const uint4*)(Ps + (wid*4 + kt)*128 + lane*4);
                #pragma unroll
                for (int p = 0; p < 8; p++){
                    int r = kt*16 + ((lane >> 3) & 1)*8 + (lane & 7);
                    int c = 2*p + (lane >> 4);
                    uint4 bq;
                    LDSM4T(bq, vb + r*256 + ((c ^ (r & 7)) << 4));
                    mma_f16(o[2*p],   pf, make_uint2(bq.x, bq.y));
                    mma_f16(o[2*p+1], pf, make_uint2(bq.z, bq.w));
                }
            }
        }
        __syncthreads();
    }

    // ---- output (fp16) ----
    float inv0 = 1.f / l0, inv1 = 1.f / l1;
    const int row_lo = q0 + wid*16 + (lane >> 2);
    const int row_hi = row_lo + 8;
    __half* olo = g_Oh + ((size_t)bz*S_LEN + row_lo)*D_MODEL + hh*HD;
    __half* ohi = g_Oh + ((size_t)bz*S_LEN + row_hi)*D_MODEL + hh*HD;
    #pragma unroll
    for (int nt = 0; nt < 16; nt++){
        int d0 = nt*8 + (lane & 3)*2;
        *(__half2*)(olo + d0) = __floats2half2_rn(o[nt][0]*inv0, o[nt][1]*inv0);
        *(__half2*)(ohi + d0) = __floats2half2_rn(o[nt][2]*inv1, o[nt][3]*inv1);
    }
}

extern "C" void kernel_launch(void* const* d_in, const int* in_sizes, int n_in,
                              void* d_out, int out_size)
{
    const float* x    = (const float*)d_in[0];
    const float* fcos = (const float*)d_in[1];
    const float* fsin = (const float*)d_in[2];
    const float* wq   = (const float*)d_in[3];
    const float* wk   = (const float*)d_in[4];
    const float* wv   = (const float*)d_in[5];
    const float* wo   = (const float*)d_in[6];
    float* out = (float*)d_out;

    __half *pXh, *pWqkv, *pWoh, *pOh;
    cudaGetSymbolAddress((void**)&pXh,  g_Xh);
    cudaGetSymbolAddress((void**)&pWqkv, g_Wqkv);
    cudaGetSymbolAddress((void**)&pWoh, g_Woh);
    cudaGetSymbolAddress((void**)&pOh,  g_Oh);

    cudaFuncSetAttribute(gemm_h<3>, cudaFuncAttributeMaxDynamicSharedMemorySize, GEMM_SMEM);
    cudaFuncSetAttribute(gemm_h<0>, cudaFuncAttributeMaxDynamicSharedMemorySize, GEMM_SMEM);
    cudaFuncSetAttribute(attn2, cudaFuncAttributeMaxDynamicSharedMemorySize, ATT_SMEM);

    // single fp32 -> fp16 prepass (x, wq, wk, wv, wo)
    cvt_all<<<CVT_TOTAL4/256, 256>>>(x, wq, wk, wv, wo);

    // fused QKV projection (+rope, scatter to [b,h,s,d] fp16)
    gemm_h<3><<<dim3(3072/256, MROWS/128), 256, GEMM_SMEM>>>(pXh, pWqkv, nullptr, fcos, fsin);
    // attention -> g_Oh [b,s,h*d] fp16
    attn2<<<dim3(S_LEN/128, B_SZ*NH), 256, ATT_SMEM>>>();
    // output projection -> d_out (f32)
    gemm_h<0><<<dim3(D_MODEL/256, MROWS/128), 256, GEMM_SMEM>>>(pOh, pWoh, out, nullptr, nullptr);
}

// round 11
// speedup vs baseline: 1.0392x; 1.0392x over previous
#include <cuda_runtime.h>
#include <cuda_fp16.h>
#include <cstdint>
#include <math.h>

#define B_SZ 2
#define S_LEN 2048
#define D_MODEL 2048
#define NH 16
#define NKVH 4
#define HD 128
#define MROWS (B_SZ*S_LEN)

// fp16 scratch (allocation-free rule: __device__ globals)
__device__ __half g_Xh[(size_t)MROWS*D_MODEL];
__device__ __half g_Wqkv[(size_t)3072*D_MODEL];     // wq(2048) | wk(512) | wv(512) rows
__device__ __half g_Woh[(size_t)D_MODEL*D_MODEL];
__device__ __half g_Qh[(size_t)B_SZ*NH*S_LEN*HD];   // [b,h,s,d] post-rope
__device__ __half g_Kh[(size_t)B_SZ*NKVH*S_LEN*HD];
__device__ __half g_Vh[(size_t)B_SZ*NKVH*S_LEN*HD];
__device__ __half g_Oh[(size_t)B_SZ*S_LEN*D_MODEL]; // [b,s,h*d]

__device__ __forceinline__ void mma_f16(float* c, const uint4& a, const uint2& b){
    asm volatile("mma.sync.aligned.m16n8k16.row.col.f32.f16.f16.f32 "
        "{%0,%1,%2,%3}, {%4,%5,%6,%7}, {%8,%9}, {%0,%1,%2,%3};"
        : "+f"(c[0]), "+f"(c[1]), "+f"(c[2]), "+f"(c[3])
        : "r"(a.x), "r"(a.y), "r"(a.z), "r"(a.w), "r"(b.x), "r"(b.y));
}
#define LDSM4(v, addr) asm volatile( \
    "ldmatrix.sync.aligned.m8n8.x4.shared.b16 {%0,%1,%2,%3}, [%4];" \
    : "=r"((v).x), "=r"((v).y), "=r"((v).z), "=r"((v).w) : "r"(addr))
#define LDSM4T(v, addr) asm volatile( \
    "ldmatrix.sync.aligned.m8n8.x4.trans.shared.b16 {%0,%1,%2,%3}, [%4];" \
    : "=r"((v).x), "=r"((v).y), "=r"((v).z), "=r"((v).w) : "r"(addr))
#define CP16(dst, src) asm volatile( \
    "cp.async.cg.shared.global [%0], [%1], 16;" :: "r"(dst), "l"(src))
#define CPCOMMIT asm volatile("cp.async.commit_group;")
#define CPWAIT(n) asm volatile("cp.async.wait_group %0;" :: "n"(n))

// ---------------- single-launch fp32 -> fp16 conversion prepass ----------------
// segments (float4 units): x 2097152 | wq 1048576 | wk 262144 | wv 262144 | wo 1048576
#define CVT_TOTAL4 4718592
__global__ void cvt_all(const float* __restrict__ x,  const float* __restrict__ wq,
                        const float* __restrict__ wk, const float* __restrict__ wv,
                        const float* __restrict__ wo)
{
    int i = blockIdx.x*256 + threadIdx.x;
    const float* s; __half* d; int off;
    if (i < 2097152)      { s = x;  d = g_Xh;                          off = i; }
    else if (i < 3145728) { s = wq; d = g_Wqkv;                        off = i - 2097152; }
    else if (i < 3407872) { s = wk; d = g_Wqkv + (size_t)2048*D_MODEL; off = i - 3145728; }
    else if (i < 3670016) { s = wv; d = g_Wqkv + (size_t)2560*D_MODEL; off = i - 3407872; }
    else                  { s = wo; d = g_Woh;                         off = i - 3670016; }
    float4 f = ((const float4*)s)[off];
    ((__half2*)d)[2*off]   = __floats2half2_rn(f.x, f.y);
    ((__half2*)d)[2*off+1] = __floats2half2_rn(f.z, f.w);
}

// ============ GEMM: C = A * W^T (fp16 in, cp.async + ldmatrix) ============
// BM=128, BN=128, BK=64, 2 stages (64KB smem), 128 threads (4 warps, 64x64).
// 3 CTAs/SM target via __launch_bounds__(128,3).
// MODE 0: C f32 row-major [M,2048].  MODE 3: fused QKV -> fp16 [b,h,s,d] + rope.
#define GEMM_SMEM (4*16384)

template<int MODE>
__global__ void __launch_bounds__(128, 3) gemm_h(
    const __half* __restrict__ A, const __half* __restrict__ Bw,
    float* __restrict__ Cf,
    const float* __restrict__ fcos, const float* __restrict__ fsin)
{
    extern __shared__ char sm[];
    const uint32_t sb = (uint32_t)__cvta_generic_to_shared(sm);
    const int tid = threadIdx.x, lane = tid & 31, wid = tid >> 5;
    const int wm = wid & 1, wn = wid >> 1;
    const int m0 = blockIdx.y * 128;
    const int n0g = blockIdx.x * 128;

    __half* Ch = nullptr; int n0 = n0g, Hn = 0, rope = 0;
    if (MODE == 3) {
        if (n0g < 2048)      { Ch = g_Qh; n0 = n0g;        Hn = NH;   rope = 1; }
        else if (n0g < 2560) { Ch = g_Kh; n0 = n0g - 2048; Hn = NKVH; rope = 1; }
        else                 { Ch = g_Vh; n0 = n0g - 2560; Hn = NKVH; rope = 0; }
    }
    const __half* Ag0 = A  + (size_t)m0  * D_MODEL;
    const __half* Bg0 = Bw + (size_t)n0g * D_MODEL;

    auto loadStage = [&](int s, int kc){
        uint32_t ab = sb + s*16384;
        uint32_t bb = sb + 32768 + s*16384;
        const __half* Ag = Ag0 + kc;
        const __half* Bg = Bg0 + kc;
        #pragma unroll
        for (int i = 0; i < 8; i++){
            int idx = tid + 128*i;
            int r = idx >> 3, c = idx & 7;
            CP16(ab + r*128 + ((c ^ (r & 7)) << 4), Ag + (size_t)r*D_MODEL + c*8);
        }
        #pragma unroll
        for (int i = 0; i < 8; i++){
            int idx = tid + 128*i;
            int r = idx >> 3, c = idx & 7;
            CP16(bb + r*128 + ((c ^ (r & 7)) << 4), Bg + (size_t)r*D_MODEL + c*8);
        }
        CPCOMMIT;
    };

    float acc[4][8][4];
    #pragma unroll
    for (int mt = 0; mt < 4; mt++)
        #pragma unroll
        for (int n = 0; n < 8; n++)
            #pragma unroll
            for (int r = 0; r < 4; r++) acc[mt][n][r] = 0.f;

    loadStage(0, 0);

    for (int i = 0; i < 32; i++){
        CPWAIT(0);
        __syncthreads();
        if (i + 1 < 32) loadStage((i+1) & 1, (i+1)*64);

        const uint32_t ab = sb + (i&1)*16384;
        const uint32_t bb = sb + 32768 + (i&1)*16384;
        #pragma unroll
        for (int kt = 0; kt < 4; kt++){
            uint4 af[4];
            #pragma unroll
            for (int mt = 0; mt < 4; mt++){
                int r = wm*64 + mt*16 + (lane & 15);
                int c = kt*2 + (lane >> 4);
                LDSM4(af[mt], ab + r*128 + ((c ^ (r & 7)) << 4));
            }
            #pragma unroll
            for (int p = 0; p < 4; p++){
                int r = wn*64 + p*16 + ((lane >> 4) << 3) + (lane & 7);
                int c = kt*2 + ((lane >> 3) & 1);
                uint4 bq;
                LDSM4(bq, bb + r*128 + ((c ^ (r & 7)) << 4));
                uint2 b0 = make_uint2(bq.x, bq.y);
                uint2 b1 = make_uint2(bq.z, bq.w);
                #pragma unroll
                for (int mt = 0; mt < 4; mt++){
                    mma_f16(acc[mt][2*p],   af[mt], b0);
                    mma_f16(acc[mt][2*p+1], af[mt], b1);
                }
            }
        }
    }

    // -------- epilogue --------
    const int l4 = lane >> 2;
    const int l2 = (lane & 3) * 2;
    #pragma unroll
    for (int mt = 0; mt < 4; mt++){
        #pragma unroll
        for (int n = 0; n < 8; n++){
            const int col = (MODE == 0 ? n0g : n0) + wn*64 + n*8 + l2;
            #pragma unroll
            for (int half = 0; half < 2; half++){
                const int row = m0 + wm*64 + mt*16 + l4 + half*8;
                float xr = acc[mt][n][half*2 + 0];
                float xi = acc[mt][n][half*2 + 1];
                if (MODE == 0){
                    float2 o; o.x = xr; o.y = xi;
                    *(float2*)(Cf + (size_t)row*D_MODEL + col) = o;
                } else {
                    const int b = row >> 11;
                    const int s = row & (S_LEN-1);
                    const int h = col >> 7;
                    const int d = col & (HD-1);
                    __half* op = Ch + (((size_t)(b*Hn + h))*S_LEN + s)*HD + d;
                    if (rope){
                        float cs = fcos[s*(HD/2) + (d>>1)];
                        float sn = fsin[s*(HD/2) + (d>>1)];
                        *(__half2*)op = __floats2half2_rn(xr*cs - xi*sn, xr*sn + xi*cs);
                    } else {
                        *(__half2*)op = __floats2half2_rn(xr, xi);
                    }
                }
            }
        }
    }
}

// ===== Flash attention v2: fp16, BQ=128, BKT=64, cp.async dbuf, ldmatrix =====
// smem: Q 32KB | K[2] 2x16KB | V[2] 2x16KB | P 16KB  = 112KB
// qt reversed so the heavy causal CTAs launch in wave 1.
#define ATT_SMEM 114688

__global__ void __launch_bounds__(256) attn2()
{
    extern __shared__ char sm[];
    const uint32_t sb = (uint32_t)__cvta_generic_to_shared(sm);
    const uint32_t Qb = sb;
    const uint32_t Kb0 = sb + 32768, Kb1 = sb + 49152;
    const uint32_t Vb0 = sb + 65536, Vb1 = sb + 81920;
    uint32_t* Ps = (uint32_t*)(sm + 98304);   // [8 mt][4 kt][128] words

    const int tid = threadIdx.x, lane = tid & 31, wid = tid >> 5;
    const int bz  = blockIdx.y >> 4;
    const int hh  = blockIdx.y & 15;
    const int kvh = hh >> 2;
    const int qt  = (gridDim.x - 1) - blockIdx.x;   // heavy tiles first
    const int q0  = qt * 128;

    const __half* Qg = g_Qh + ((size_t)(bz*NH   + hh )*S_LEN + q0)*HD;
    const __half* Kg = g_Kh + ((size_t)(bz*NKVH + kvh)*S_LEN)*HD;
    const __half* Vg = g_Vh + ((size_t)(bz*NKVH + kvh)*S_LEN)*HD;

    auto loadKV = [&](int buf, int k0){
        uint32_t kb = buf ? Kb1 : Kb0;
        uint32_t vb = buf ? Vb1 : Vb0;
        #pragma unroll
        for (int i = 0; i < 4; i++){
            int idx = tid + 256*i;
            int r = idx >> 4, c = idx & 15;
            uint32_t off = r*256 + ((c ^ (r & 7)) << 4);
            CP16(kb + off, Kg + (size_t)(k0 + r)*HD + c*8);
            CP16(vb + off, Vg + (size_t)(k0 + r)*HD + c*8);
        }
        CPCOMMIT;
    };

    // group 0: Q + KV(0)
    #pragma unroll
    for (int i = 0; i < 8; i++){
        int idx = tid + 256*i;
        int r = idx >> 4, c = idx & 15;
        CP16(Qb + r*256 + ((c ^ (r & 7)) << 4), Qg + (size_t)r*HD + c*8);
    }
    loadKV(0, 0);

    const int nkt = 2*qt + 2;
    const float scale = 0.08838834764831845f;   // 1/sqrt(128)
    const int qlo = q0 + wid*16 + (lane >> 2);
    const int qhi = qlo + 8;
    const int diagTile = 2*qt + (wid >= 4 ? 1 : 0);

    uint4 qf[8];
    float m0 = -1e30f, m1 = -1e30f, l0 = 0.f, l1 = 0.f;
    float o[16][4];
    #pragma unroll
    for (int nt = 0; nt < 16; nt++)
        #pragma unroll
        for (int r = 0; r < 4; r++) o[nt][r] = 0.f;

    for (int tile = 0; tile < nkt; tile++){
        if (tile + 1 < nkt) { loadKV((tile+1) & 1, (tile+1)*64); CPWAIT(1); }
        else                { CPWAIT(0); }
        __syncthreads();

        if (tile == 0){
            #pragma unroll
            for (int kt = 0; kt < 8; kt++){
                int r = wid*16 + (lane & 15);
                int c = kt*2 + (lane >> 4);
                LDSM4(qf[kt], Qb + r*256 + ((c ^ (r & 7)) << 4));
            }
        }

        const int k0 = tile * 64;
        const bool skip = (tile == 2*qt + 1) && (wid < 4);
        if (!skip){
            const uint32_t kb = (tile & 1) ? Kb1 : Kb0;
            const uint32_t vb = (tile & 1) ? Vb1 : Vb0;

            // ---- S = Q K^T (16 x 64 per warp) ----
            float sacc[8][4];
            #pragma unroll
            for (int n = 0; n < 8; n++)
                #pragma unroll
                for (int r = 0; r < 4; r++) sacc[n][r] = 0.f;
            #pragma unroll
            for (int kt = 0; kt < 8; kt++){
                #pragma unroll
                for (int p = 0; p < 4; p++){
                    int r = p*16 + ((lane >> 4) << 3) + (lane & 7);
                    int c = kt*2 + ((lane >> 3) & 1);
                    uint4 bq;
                    LDSM4(bq, kb + r*256 + ((c ^ (r & 7)) << 4));
                    mma_f16(sacc[2*p],   qf[kt], make_uint2(bq.x, bq.y));
                    mma_f16(sacc[2*p+1], qf[kt], make_uint2(bq.z, bq.w));
                }
            }

            // ---- online softmax ----
            const bool diag = (tile == diagTile);
            float mx0 = -1e30f, mx1 = -1e30f;
            #pragma unroll
            for (int n = 0; n < 8; n++){
                float v0 = sacc[n][0]*scale, v1 = sacc[n][1]*scale;
                float v2 = sacc[n][2]*scale, v3 = sacc[n][3]*scale;
                if (diag){
                    int c0 = k0 + n*8 + (lane & 3)*2;
                    if (c0     > qlo) v0 = -1e30f;
                    if (c0 + 1 > qlo) v1 = -1e30f;
                    if (c0     > qhi) v2 = -1e30f;
                    if (c0 + 1 > qhi) v3 = -1e30f;
                }
                sacc[n][0]=v0; sacc[n][1]=v1; sacc[n][2]=v2; sacc[n][3]=v3;
                mx0 = fmaxf(mx0, fmaxf(v0, v1));
                mx1 = fmaxf(mx1, fmaxf(v2, v3));
            }
            mx0 = fmaxf(mx0, __shfl_xor_sync(0xffffffffu, mx0, 1));
            mx0 = fmaxf(mx0, __shfl_xor_sync(0xffffffffu, mx0, 2));
            mx1 = fmaxf(mx1, __shfl_xor_sync(0xffffffffu, mx1, 1));
            mx1 = fmaxf(mx1, __shfl_xor_sync(0xffffffffu, mx1, 2));
            float nm0 = fmaxf(m0, mx0), nm1 = fmaxf(m1, mx1);
            float cr0 = __expf(m0 - nm0), cr1 = __expf(m1 - nm1);
            m0 = nm0; m1 = nm1;

            float s0 = 0.f, s1 = 0.f;
            #pragma unroll
            for (int n = 0; n < 8; n++){
                float p0 = __expf(sacc[n][0] - nm0);
                float p1 = __expf(sacc[n][1] - nm0);
                float p2 = __expf(sacc[n][2] - nm1);
                float p3 = __expf(sacc[n][3] - nm1);
                s0 += p0 + p1; s1 += p2 + p3;
                __half2 w0 = __floats2half2_rn(p0, p1);
                __half2 w1 = __floats2half2_rn(p2, p3);
                uint2 w; w.x = *(uint32_t*)&w0; w.y = *(uint32_t*)&w1;
                *(uint2*)(Ps + (wid*4 + (n>>1))*128 + (lane>>2)*16 + (lane&3)*4 + 2*(n&1)) = w;
            }
            s0 += __shfl_xor_sync(0xffffffffu, s0, 1);
            s0 += __shfl_xor_sync(0xffffffffu, s0, 2);
            s1 += __shfl_xor_sync(0xffffffffu, s1, 1);
            s1 += __shfl_xor_sync(0xffffffffu, s1, 2);
            l0 = l0*cr0 + s0;
            l1 = l1*cr1 + s1;
            #pragma unroll
            for (int nt = 0; nt < 16; nt++){
                o[nt][0] *= cr0; o[nt][1] *= cr0;
                o[nt][2] *= cr1; o[nt][3] *= cr1;
            }
            __syncwarp();

            // ---- O += P V (16 x 128 per warp) ----
            #pragma unroll
            for (int kt = 0; kt < 4; kt++){
                uint4 pf = *(const uint4*)(Ps + (wid*4 + kt)*128 + lane*4);
                #pragma unroll
                for (int p = 0; p < 8; p++){
                    int r = kt*16 + ((lane >> 3) & 1)*8 + (lane & 7);
                    int c = 2*p + (lane >> 4);
                    uint4 bq;
                    LDSM4T(bq, vb + r*256 + ((c ^ (r & 7)) << 4));
                    mma_f16(o[2*p],   pf, make_uint2(bq.x, bq.y));
                    mma_f16(o[2*p+1], pf, make_uint2(bq.z, bq.w));
                }
            }
        }
        __syncthreads();
    }

    // ---- output (fp16) ----
    float inv0 = 1.f / l0, inv1 = 1.f / l1;
    const int row_lo = q0 + wid*16 + (lane >> 2);
    const int row_hi = row_lo + 8;
    __half* olo = g_Oh + ((size_t)bz*S_LEN + row_lo)*D_MODEL + hh*HD;
    __half* ohi = g_Oh + ((size_t)bz*S_LEN + row_hi)*D_MODEL + hh*HD;
    #pragma unroll
    for (int nt = 0; nt < 16; nt++){
        int d0 = nt*8 + (lane & 3)*2;
        *(__half2*)(olo + d0) = __floats2half2_rn(o[nt][0]*inv0, o[nt][1]*inv0);
        *(__half2*)(ohi + d0) = __floats2half2_rn(o[nt][2]*inv1, o[nt][3]*inv1);
    }
}

extern "C" void kernel_launch(void* const* d_in, const int* in_sizes, int n_in,
                              void* d_out, int out_size)
{
    const float* x    = (const float*)d_in[0];
    const float* fcos = (const float*)d_in[1];
    const float* fsin = (const float*)d_in[2];
    const float* wq   = (const float*)d_in[3];
    const float* wk   = (const float*)d_in[4];
    const float* wv   = (const float*)d_in[5];
    const float* wo   = (const float*)d_in[6];
    float* out = (float*)d_out;

    __half *pXh, *pWqkv, *pWoh, *pOh;
    cudaGetSymbolAddress((void**)&pXh,  g_Xh);
    cudaGetSymbolAddress((void**)&pWqkv, g_Wqkv);
    cudaGetSymbolAddress((void**)&pWoh, g_Woh);
    cudaGetSymbolAddress((void**)&pOh,  g_Oh);

    cudaFuncSetAttribute(gemm_h<3>, cudaFuncAttributeMaxDynamicSharedMemorySize, GEMM_SMEM);
    cudaFuncSetAttribute(gemm_h<0>, cudaFuncAttributeMaxDynamicSharedMemorySize, GEMM_SMEM);
    cudaFuncSetAttribute(attn2, cudaFuncAttributeMaxDynamicSharedMemorySize, ATT_SMEM);

    // single fp32 -> fp16 prepass (x, wq, wk, wv, wo)
    cvt_all<<<CVT_TOTAL4/256, 256>>>(x, wq, wk, wv, wo);

    // fused QKV projection (+rope, scatter to [b,h,s,d] fp16)
    gemm_h<3><<<dim3(3072/128, MROWS/128), 128, GEMM_SMEM>>>(pXh, pWqkv, nullptr, fcos, fsin);
    // attention -> g_Oh [b,s,h*d] fp16
    attn2<<<dim3(S_LEN/128, B_SZ*NH), 256, ATT_SMEM>>>();
    // output projection -> d_out (f32)
    gemm_h<0><<<dim3(D_MODEL/128, MROWS/128), 128, GEMM_SMEM>>>(pOh, pWoh, out, nullptr, nullptr);
}

// round 13
// speedup vs baseline: 1.1562x; 1.1127x over previous
#include <cuda_runtime.h>
#include <cuda_fp16.h>
#include <cstdint>
#include <math.h>

#define B_SZ 2
#define S_LEN 2048
#define D_MODEL 2048
#define NH 16
#define NKVH 4
#define HD 128
#define MROWS (B_SZ*S_LEN)

// fp16 scratch (allocation-free rule: __device__ globals)
__device__ __half g_Xh[(size_t)MROWS*D_MODEL];
__device__ __half g_Wqkv[(size_t)3072*D_MODEL];     // wq(2048) | wk(512) | wv(512) rows
__device__ __half g_Woh[(size_t)D_MODEL*D_MODEL];
__device__ __half g_Qh[(size_t)B_SZ*NH*S_LEN*HD];   // [b,h,s,d] post-rope
__device__ __half g_Kh[(size_t)B_SZ*NKVH*S_LEN*HD];
__device__ __half g_Vh[(size_t)B_SZ*NKVH*S_LEN*HD];
__device__ __half g_Oh[(size_t)B_SZ*S_LEN*D_MODEL]; // [b,s,h*d]

__device__ __forceinline__ void mma_f16(float* c, const uint4& a, const uint2& b){
    asm volatile("mma.sync.aligned.m16n8k16.row.col.f32.f16.f16.f32 "
        "{%0,%1,%2,%3}, {%4,%5,%6,%7}, {%8,%9}, {%0,%1,%2,%3};"
        : "+f"(c[0]), "+f"(c[1]), "+f"(c[2]), "+f"(c[3])
        : "r"(a.x), "r"(a.y), "r"(a.z), "r"(a.w), "r"(b.x), "r"(b.y));
}
#define LDSM4(v, addr) asm volatile( \
    "ldmatrix.sync.aligned.m8n8.x4.shared.b16 {%0,%1,%2,%3}, [%4];" \
    : "=r"((v).x), "=r"((v).y), "=r"((v).z), "=r"((v).w) : "r"(addr))
#define LDSM4T(v, addr) asm volatile( \
    "ldmatrix.sync.aligned.m8n8.x4.trans.shared.b16 {%0,%1,%2,%3}, [%4];" \
    : "=r"((v).x), "=r"((v).y), "=r"((v).z), "=r"((v).w) : "r"(addr))
#define CP16(dst, src) asm volatile( \
    "cp.async.cg.shared.global [%0], [%1], 16;" :: "r"(dst), "l"(src))
#define CPCOMMIT asm volatile("cp.async.commit_group;")
#define CPWAIT(n) asm volatile("cp.async.wait_group %0;" :: "n"(n))

// ---------------- single-launch fp32 -> fp16 conversion prepass ----------------
// segments (float4 units): x 2097152 | wq 1048576 | wk 262144 | wv 262144 | wo 1048576
#define CVT_TOTAL4 4718592
__global__ void cvt_all(const float* __restrict__ x,  const float* __restrict__ wq,
                        const float* __restrict__ wk, const float* __restrict__ wv,
                        const float* __restrict__ wo)
{
    int i = blockIdx.x*256 + threadIdx.x;
    const float* s; __half* d; int off;
    if (i < 2097152)      { s = x;  d = g_Xh;                          off = i; }
    else if (i < 3145728) { s = wq; d = g_Wqkv;                        off = i - 2097152; }
    else if (i < 3407872) { s = wk; d = g_Wqkv + (size_t)2048*D_MODEL; off = i - 3145728; }
    else if (i < 3670016) { s = wv; d = g_Wqkv + (size_t)2560*D_MODEL; off = i - 3407872; }
    else                  { s = wo; d = g_Woh;                         off = i - 3670016; }
    float4 f = ((const float4*)s)[off];
    ((__half2*)d)[2*off]   = __floats2half2_rn(f.x, f.y);
    ((__half2*)d)[2*off+1] = __floats2half2_rn(f.z, f.w);
}

// ============ GEMM: C = A * W^T (fp16 in, cp.async + ldmatrix) ============
// BM=64, BN=128, BK=64, 2 stages (48KB smem), 128 threads (2x2 warps, 32x64).
// 4 CTAs/SM target via __launch_bounds__(128,4).
// MODE 0: C f32 row-major [M,2048].  MODE 3: fused QKV -> fp16 [b,h,s,d] + rope.
#define A_ST 8192
#define B_ST 16384
#define GEMM_SMEM (2*(A_ST + B_ST))

template<int MODE>
__global__ void __launch_bounds__(128, 4) gemm_h(
    const __half* __restrict__ A, const __half* __restrict__ Bw,
    float* __restrict__ Cf,
    const float* __restrict__ fcos, const float* __restrict__ fsin)
{
    extern __shared__ char sm[];
    const uint32_t sb = (uint32_t)__cvta_generic_to_shared(sm);
    const int tid = threadIdx.x, lane = tid & 31, wid = tid >> 5;
    const int wm = wid & 1, wn = wid >> 1;          // 2x2 warps, 32x64 tiles
    const int m0 = blockIdx.y * 64;
    const int n0g = blockIdx.x * 128;

    __half* Ch = nullptr; int n0 = n0g, Hn = 0, rope = 0;
    if (MODE == 3) {
        if (n0g < 2048)      { Ch = g_Qh; n0 = n0g;        Hn = NH;   rope = 1; }
        else if (n0g < 2560) { Ch = g_Kh; n0 = n0g - 2048; Hn = NKVH; rope = 1; }
        else                 { Ch = g_Vh; n0 = n0g - 2560; Hn = NKVH; rope = 0; }
    }
    const __half* Ag0 = A  + (size_t)m0  * D_MODEL;
    const __half* Bg0 = Bw + (size_t)n0g * D_MODEL;

    auto loadStage = [&](int s, int kc){
        uint32_t ab = sb + s*A_ST;
        uint32_t bb = sb + 2*A_ST + s*B_ST;
        const __half* Ag = Ag0 + kc;
        const __half* Bg = Bg0 + kc;
        #pragma unroll
        for (int i = 0; i < 4; i++){            // A: 64x64 fp16 = 512 x 16B
            int idx = tid + 128*i;
            int r = idx >> 3, c = idx & 7;
            CP16(ab + r*128 + ((c ^ (r & 7)) << 4), Ag + (size_t)r*D_MODEL + c*8);
        }
        #pragma unroll
        for (int i = 0; i < 8; i++){            // B: 128x64 fp16 = 1024 x 16B
            int idx = tid + 128*i;
            int r = idx >> 3, c = idx & 7;
            CP16(bb + r*128 + ((c ^ (r & 7)) << 4), Bg + (size_t)r*D_MODEL + c*8);
        }
        CPCOMMIT;
    };

    float acc[2][8][4];
    #pragma unroll
    for (int mt = 0; mt < 2; mt++)
        #pragma unroll
        for (int n = 0; n < 8; n++)
            #pragma unroll
            for (int r = 0; r < 4; r++) acc[mt][n][r] = 0.f;

    loadStage(0, 0);

    for (int i = 0; i < 32; i++){
        CPWAIT(0);
        __syncthreads();
        if (i + 1 < 32) loadStage((i+1) & 1, (i+1)*64);

        const uint32_t ab = sb + (i&1)*A_ST;
        const uint32_t bb = sb + 2*A_ST + (i&1)*B_ST;
        #pragma unroll
        for (int kt = 0; kt < 4; kt++){
            uint4 af[2];
            #pragma unroll
            for (int mt = 0; mt < 2; mt++){
                int r = wm*32 + mt*16 + (lane & 15);
                int c = kt*2 + (lane >> 4);
                LDSM4(af[mt], ab + r*128 + ((c ^ (r & 7)) << 4));
            }
            #pragma unroll
            for (int p = 0; p < 4; p++){
                int r = wn*64 + p*16 + ((lane >> 4) << 3) + (lane & 7);
                int c = kt*2 + ((lane >> 3) & 1);
                uint4 bq;
                LDSM4(bq, bb + r*128 + ((c ^ (r & 7)) << 4));
                uint2 b0 = make_uint2(bq.x, bq.y);
                uint2 b1 = make_uint2(bq.z, bq.w);
                #pragma unroll
                for (int mt = 0; mt < 2; mt++){
                    mma_f16(acc[mt][2*p],   af[mt], b0);
                    mma_f16(acc[mt][2*p+1], af[mt], b1);
                }
            }
        }
    }

    // -------- epilogue --------
    const int l4 = lane >> 2;
    const int l2 = (lane & 3) * 2;
    #pragma unroll
    for (int mt = 0; mt < 2; mt++){
        #pragma unroll
        for (int n = 0; n < 8; n++){
            const int col = (MODE == 0 ? n0g : n0) + wn*64 + n*8 + l2;
            #pragma unroll
            for (int half = 0; half < 2; half++){
                const int row = m0 + wm*32 + mt*16 + l4 + half*8;
                float xr = acc[mt][n][half*2 + 0];
                float xi = acc[mt][n][half*2 + 1];
                if (MODE == 0){
                    float2 o; o.x = xr; o.y = xi;
                    *(float2*)(Cf + (size_t)row*D_MODEL + col) = o;
                } else {
                    const int b = row >> 11;
                    const int s = row & (S_LEN-1);
                    const int h = col >> 7;
                    const int d = col & (HD-1);
                    __half* op = Ch + (((size_t)(b*Hn + h))*S_LEN + s)*HD + d;
                    if (rope){
                        float cs = fcos[s*(HD/2) + (d>>1)];
                        float sn = fsin[s*(HD/2) + (d>>1)];
                        *(__half2*)op = __floats2half2_rn(xr*cs - xi*sn, xr*sn + xi*cs);
                    } else {
                        *(__half2*)op = __floats2half2_rn(xr, xi);
                    }
                }
            }
        }
    }
}

// ===== Flash attention v2: fp16, BQ=128, BKT=64, cp.async dbuf, ldmatrix =====
// smem: Q 32KB | K[2] 2x16KB | V[2] 2x16KB | P 16KB  = 112KB
// qt reversed so the heavy causal CTAs launch in wave 1.
#define ATT_SMEM 114688

__global__ void __launch_bounds__(256) attn2()
{
    extern __shared__ char sm[];
    const uint32_t sb = (uint32_t)__cvta_generic_to_shared(sm);
    const uint32_t Qb = sb;
    const uint32_t Kb0 = sb + 32768, Kb1 = sb + 49152;
    const uint32_t Vb0 = sb + 65536, Vb1 = sb + 81920;
    uint32_t* Ps = (uint32_t*)(sm + 98304);   // [8 mt][4 kt][128] words

    const int tid = threadIdx.x, lane = tid & 31, wid = tid >> 5;
    const int bz  = blockIdx.y >> 4;
    const int hh  = blockIdx.y & 15;
    const int kvh = hh >> 2;
    const int qt  = (gridDim.x - 1) - blockIdx.x;   // heavy tiles first
    const int q0  = qt * 128;

    const __half* Qg = g_Qh + ((size_t)(bz*NH   + hh )*S_LEN + q0)*HD;
    const __half* Kg = g_Kh + ((size_t)(bz*NKVH + kvh)*S_LEN)*HD;
    const __half* Vg = g_Vh + ((size_t)(bz*NKVH + kvh)*S_LEN)*HD;

    auto loadKV = [&](int buf, int k0){
        uint32_t kb = buf ? Kb1 : Kb0;
        uint32_t vb = buf ? Vb1 : Vb0;
        #pragma unroll
        for (int i = 0; i < 4; i++){
            int idx = tid + 256*i;
            int r = idx >> 4, c = idx & 15;
            uint32_t off = r*256 + ((c ^ (r & 7)) << 4);
            CP16(kb + off, Kg + (size_t)(k0 + r)*HD + c*8);
            CP16(vb + off, Vg + (size_t)(k0 + r)*HD + c*8);
        }
        CPCOMMIT;
    };

    // group 0: Q + KV(0)
    #pragma unroll
    for (int i = 0; i < 8; i++){
        int idx = tid + 256*i;
        int r = idx >> 4, c = idx & 15;
        CP16(Qb + r*256 + ((c ^ (r & 7)) << 4), Qg + (size_t)r*HD + c*8);
    }
    loadKV(0, 0);

    const int nkt = 2*qt + 2;
    const float scale = 0.08838834764831845f;   // 1/sqrt(128)
    const int qlo = q0 + wid*16 + (lane >> 2);
    const int qhi = qlo + 8;
    const int diagTile = 2*qt + (wid >= 4 ? 1 : 0);

    uint4 qf[8];
    float m0 = -1e30f, m1 = -1e30f, l0 = 0.f, l1 = 0.f;
    float o[16][4];
    #pragma unroll
    for (int nt = 0; nt < 16; nt++)
        #pragma unroll
        for (int r = 0; r < 4; r++) o[nt][r] = 0.f;

    for (int tile = 0; tile < nkt; tile++){
        if (tile + 1 < nkt) { loadKV((tile+1) & 1, (tile+1)*64); CPWAIT(1); }
        else                { CPWAIT(0); }
        __syncthreads();

        if (tile == 0){
            #pragma unroll
            for (int kt = 0; kt < 8; kt++){
                int r = wid*16 + (lane & 15);
                int c = kt*2 + (lane >> 4);
                LDSM4(qf[kt], Qb + r*256 + ((c ^ (r & 7)) << 4));
            }
        }

        const int k0 = tile * 64;
        const bool skip = (tile == 2*qt + 1) && (wid < 4);
        if (!skip){
            const uint32_t kb = (tile & 1) ? Kb1 : Kb0;
            const uint32_t vb = (tile & 1) ? Vb1 : Vb0;

            // ---- S = Q K^T (16 x 64 per warp) ----
            float sacc[8][4];
            #pragma unroll
            for (int n = 0; n < 8; n++)
                #pragma unroll
                for (int r = 0; r < 4; r++) sacc[n][r] = 0.f;
            #pragma unroll
            for (int kt = 0; kt < 8; kt++){
                #pragma unroll
                for (int p = 0; p < 4; p++){
                    int r = p*16 + ((lane >> 4) << 3) + (lane & 7);
                    int c = kt*2 + ((lane >> 3) & 1);
                    uint4 bq;
                    LDSM4(bq, kb + r*256 + ((c ^ (r & 7)) << 4));
                    mma_f16(sacc[2*p],   qf[kt], make_uint2(bq.x, bq.y));
                    mma_f16(sacc[2*p+1], qf[kt], make_uint2(bq.z, bq.w));
                }
            }

            // ---- online softmax ----
            const bool diag = (tile == diagTile);
            float mx0 = -1e30f, mx1 = -1e30f;
            #pragma unroll
            for (int n = 0; n < 8; n++){
                float v0 = sacc[n][0]*scale, v1 = sacc[n][1]*scale;
                float v2 = sacc[n][2]*scale, v3 = sacc[n][3]*scale;
                if (diag){
                    int c0 = k0 + n*8 + (lane & 3)*2;
                    if (c0     > qlo) v0 = -1e30f;
                    if (c0 + 1 > qlo) v1 = -1e30f;
                    if (c0     > qhi) v2 = -1e30f;
                    if (c0 + 1 > qhi) v3 = -1e30f;
                }
                sacc[n][0]=v0; sacc[n][1]=v1; sacc[n][2]=v2; sacc[n][3]=v3;
                mx0 = fmaxf(mx0, fmaxf(v0, v1));
                mx1 = fmaxf(mx1, fmaxf(v2, v3));
            }
            mx0 = fmaxf(mx0, __shfl_xor_sync(0xffffffffu, mx0, 1));
            mx0 = fmaxf(mx0, __shfl_xor_sync(0xffffffffu, mx0, 2));
            mx1 = fmaxf(mx1, __shfl_xor_sync(0xffffffffu, mx1, 1));
            mx1 = fmaxf(mx1, __shfl_xor_sync(0xffffffffu, mx1, 2));
            float nm0 = fmaxf(m0, mx0), nm1 = fmaxf(m1, mx1);
            float cr0 = __expf(m0 - nm0), cr1 = __expf(m1 - nm1);
            m0 = nm0; m1 = nm1;

            float s0 = 0.f, s1 = 0.f;
            #pragma unroll
            for (int n = 0; n < 8; n++){
                float p0 = __expf(sacc[n][0] - nm0);
                float p1 = __expf(sacc[n][1] - nm0);
                float p2 = __expf(sacc[n][2] - nm1);
                float p3 = __expf(sacc[n][3] - nm1);
                s0 += p0 + p1; s1 += p2 + p3;
                __half2 w0 = __floats2half2_rn(p0, p1);
                __half2 w1 = __floats2half2_rn(p2, p3);
                uint2 w; w.x = *(uint32_t*)&w0; w.y = *(uint32_t*)&w1;
                *(uint2*)(Ps + (wid*4 + (n>>1))*128 + (lane>>2)*16 + (lane&3)*4 + 2*(n&1)) = w;
            }
            s0 += __shfl_xor_sync(0xffffffffu, s0, 1);
            s0 += __shfl_xor_sync(0xffffffffu, s0, 2);
            s1 += __shfl_xor_sync(0xffffffffu, s1, 1);
            s1 += __shfl_xor_sync(0xffffffffu, s1, 2);
            l0 = l0*cr0 + s0;
            l1 = l1*cr1 + s1;
            #pragma unroll
            for (int nt = 0; nt < 16; nt++){
                o[nt][0] *= cr0; o[nt][1] *= cr0;
                o[nt][2] *= cr1; o[nt][3] *= cr1;
            }
            __syncwarp();

            // ---- O += P V (16 x 128 per warp) ----
            #pragma unroll
            for (int kt = 0; kt < 4; kt++){
                uint4 pf = *(const uint4*)(Ps + (wid*4 + kt)*128 + lane*4);
                #pragma unroll
                for (int p = 0; p < 8; p++){
                    int r = kt*16 + ((lane >> 3) & 1)*8 + (lane & 7);
                    int c = 2*p + (lane >> 4);
                    uint4 bq;
                    LDSM4T(bq, vb + r*256 + ((c ^ (r & 7)) << 4));
                    mma_f16(o[2*p],   pf, make_uint2(bq.x, bq.y));
                    mma_f16(o[2*p+1], pf, make_uint2(bq.z, bq.w));
                }
            }
        }
        __syncthreads();
    }

    // ---- output (fp16) ----
    float inv0 = 1.f / l0, inv1 = 1.f / l1;
    const int row_lo = q0 + wid*16 + (lane >> 2);
    const int row_hi = row_lo + 8;
    __half* olo = g_Oh + ((size_t)bz*S_LEN + row_lo)*D_MODEL + hh*HD;
    __half* ohi = g_Oh + ((size_t)bz*S_LEN + row_hi)*D_MODEL + hh*HD;
    #pragma unroll
    for (int nt = 0; nt < 16; nt++){
        int d0 = nt*8 + (lane & 3)*2;
        *(__half2*)(olo + d0) = __floats2half2_rn(o[nt][0]*inv0, o[nt][1]*inv0);
        *(__half2*)(ohi + d0) = __floats2half2_rn(o[nt][2]*inv1, o[nt][3]*inv1);
    }
}

extern "C" void kernel_launch(void* const* d_in, const int* in_sizes, int n_in,
                              void* d_out, int out_size)
{
    const float* x    = (const float*)d_in[0];
    const float* fcos = (const float*)d_in[1];
    const float* fsin = (const float*)d_in[2];
    const float* wq   = (const float*)d_in[3];
    const float* wk   = (const float*)d_in[4];
    const float* wv   = (const float*)d_in[5];
    const float* wo   = (const float*)d_in[6];
    float* out = (float*)d_out;

    __half *pXh, *pWqkv, *pWoh, *pOh;
    cudaGetSymbolAddress((void**)&pXh,  g_Xh);
    cudaGetSymbolAddress((void**)&pWqkv, g_Wqkv);
    cudaGetSymbolAddress((void**)&pWoh, g_Woh);
    cudaGetSymbolAddress((void**)&pOh,  g_Oh);

    cudaFuncSetAttribute(gemm_h<3>, cudaFuncAttributeMaxDynamicSharedMemorySize, GEMM_SMEM);
    cudaFuncSetAttribute(gemm_h<0>, cudaFuncAttributeMaxDynamicSharedMemorySize, GEMM_SMEM);
    cudaFuncSetAttribute(attn2, cudaFuncAttributeMaxDynamicSharedMemorySize, ATT_SMEM);

    // single fp32 -> fp16 prepass (x, wq, wk, wv, wo)
    cvt_all<<<CVT_TOTAL4/256, 256>>>(x, wq, wk, wv, wo);

    // fused QKV projection (+rope, scatter to [b,h,s,d] fp16)
    gemm_h<3><<<dim3(3072/128, MROWS/64), 128, GEMM_SMEM>>>(pXh, pWqkv, nullptr, fcos, fsin);
    // attention -> g_Oh [b,s,h*d] fp16
    attn2<<<dim3(S_LEN/128, B_SZ*NH), 256, ATT_SMEM>>>();
    // output projection -> d_out (f32)
    gemm_h<0><<<dim3(D_MODEL/128, MROWS/64), 128, GEMM_SMEM>>>(pOh, pWoh, out, nullptr, nullptr);
}

// round 16
// speedup vs baseline: 1.3003x; 1.1246x over previous
#include <cuda_runtime.h>
#include <cuda_fp16.h>
#include <cstdint>
#include <math.h>

#define B_SZ 2
#define S_LEN 2048
#define D_MODEL 2048
#define NH 16
#define NKVH 4
#define HD 128
#define MROWS (B_SZ*S_LEN)

// fp16 scratch (allocation-free rule: __device__ globals)
__device__ __half g_Xh[(size_t)MROWS*D_MODEL];
__device__ __half g_Wqkv[(size_t)3072*D_MODEL];     // wq(2048) | wk(512) | wv(512) rows
__device__ __half g_Woh[(size_t)D_MODEL*D_MODEL];
__device__ __half g_Qh[(size_t)B_SZ*NH*S_LEN*HD];   // [b,h,s,d] post-rope
__device__ __half g_Kh[(size_t)B_SZ*NKVH*S_LEN*HD];
__device__ __half g_Vh[(size_t)B_SZ*NKVH*S_LEN*HD];
__device__ __half g_Oh[(size_t)B_SZ*S_LEN*D_MODEL]; // [b,s,h*d]

__device__ __forceinline__ void mma_f16(float* c, const uint4& a, const uint2& b){
    asm volatile("mma.sync.aligned.m16n8k16.row.col.f32.f16.f16.f32 "
        "{%0,%1,%2,%3}, {%4,%5,%6,%7}, {%8,%9}, {%0,%1,%2,%3};"
        : "+f"(c[0]), "+f"(c[1]), "+f"(c[2]), "+f"(c[3])
        : "r"(a.x), "r"(a.y), "r"(a.z), "r"(a.w), "r"(b.x), "r"(b.y));
}
#define LDSM4(v, addr) asm volatile( \
    "ldmatrix.sync.aligned.m8n8.x4.shared.b16 {%0,%1,%2,%3}, [%4];" \
    : "=r"((v).x), "=r"((v).y), "=r"((v).z), "=r"((v).w) : "r"(addr))
#define LDSM4T(v, addr) asm volatile( \
    "ldmatrix.sync.aligned.m8n8.x4.trans.shared.b16 {%0,%1,%2,%3}, [%4];" \
    : "=r"((v).x), "=r"((v).y), "=r"((v).z), "=r"((v).w) : "r"(addr))
#define CP16(dst, src) asm volatile( \
    "cp.async.cg.shared.global [%0], [%1], 16;" :: "r"(dst), "l"(src))
#define CPCOMMIT asm volatile("cp.async.commit_group;")
#define CPWAIT(n) asm volatile("cp.async.wait_group %0;" :: "n"(n))

// ---------------- single-launch fp32 -> fp16 conversion prepass ----------------
// segments (float4 units): x 2097152 | wq 1048576 | wk 262144 | wv 262144 | wo 1048576
#define CVT_TOTAL4 4718592
__global__ void cvt_all(const float* __restrict__ x,  const float* __restrict__ wq,
                        const float* __restrict__ wk, const float* __restrict__ wv,
                        const float* __restrict__ wo)
{
    int i = blockIdx.x*256 + threadIdx.x;
    const float* s; __half* d; int off;
    if (i < 2097152)      { s = x;  d = g_Xh;                          off = i; }
    else if (i < 3145728) { s = wq; d = g_Wqkv;                        off = i - 2097152; }
    else if (i < 3407872) { s = wk; d = g_Wqkv + (size_t)2048*D_MODEL; off = i - 3145728; }
    else if (i < 3670016) { s = wv; d = g_Wqkv + (size_t)2560*D_MODEL; off = i - 3407872; }
    else                  { s = wo; d = g_Woh;                         off = i - 3670016; }
    float4 f = ((const float4*)s)[off];
    ((__half2*)d)[2*off]   = __floats2half2_rn(f.x, f.y);
    ((__half2*)d)[2*off+1] = __floats2half2_rn(f.z, f.w);
}

// ============ GEMM: C = A * W^T (fp16 in, cp.async + ldmatrix) ============
// BM=64, BN=128, BK=64, 2 stages (48KB smem), 128 threads (2x2 warps, 32x64).
// 4 CTAs/SM target via __launch_bounds__(128,4).
// MODE 0: C f32 row-major [M,2048].  MODE 3: fused QKV -> fp16 [b,h,s,d] + rope.
#define A_ST 8192
#define B_ST 16384
#define GEMM_SMEM (2*(A_ST + B_ST))

template<int MODE>
__global__ void __launch_bounds__(128, 4) gemm_h(
    const __half* __restrict__ A, const __half* __restrict__ Bw,
    float* __restrict__ Cf,
    const float* __restrict__ fcos, const float* __restrict__ fsin)
{
    extern __shared__ char sm[];
    const uint32_t sb = (uint32_t)__cvta_generic_to_shared(sm);
    const int tid = threadIdx.x, lane = tid & 31, wid = tid >> 5;
    const int wm = wid & 1, wn = wid >> 1;          // 2x2 warps, 32x64 tiles
    const int m0 = blockIdx.y * 64;
    const int n0g = blockIdx.x * 128;

    __half* Ch = nullptr; int n0 = n0g, Hn = 0, rope = 0;
    if (MODE == 3) {
        if (n0g < 2048)      { Ch = g_Qh; n0 = n0g;        Hn = NH;   rope = 1; }
        else if (n0g < 2560) { Ch = g_Kh; n0 = n0g - 2048; Hn = NKVH; rope = 1; }
        else                 { Ch = g_Vh; n0 = n0g - 2560; Hn = NKVH; rope = 0; }
    }
    const __half* Ag0 = A  + (size_t)m0  * D_MODEL;
    const __half* Bg0 = Bw + (size_t)n0g * D_MODEL;

    auto loadStage = [&](int s, int kc){
        uint32_t ab = sb + s*A_ST;
        uint32_t bb = sb + 2*A_ST + s*B_ST;
        const __half* Ag = Ag0 + kc;
        const __half* Bg = Bg0 + kc;
        #pragma unroll
        for (int i = 0; i < 4; i++){            // A: 64x64 fp16 = 512 x 16B
            int idx = tid + 128*i;
            int r = idx >> 3, c = idx & 7;
            CP16(ab + r*128 + ((c ^ (r & 7)) << 4), Ag + (size_t)r*D_MODEL + c*8);
        }
        #pragma unroll
        for (int i = 0; i < 8; i++){            // B: 128x64 fp16 = 1024 x 16B
            int idx = tid + 128*i;
            int r = idx >> 3, c = idx & 7;
            CP16(bb + r*128 + ((c ^ (r & 7)) << 4), Bg + (size_t)r*D_MODEL + c*8);
        }
        CPCOMMIT;
    };

    float acc[2][8][4];
    #pragma unroll
    for (int mt = 0; mt < 2; mt++)
        #pragma unroll
        for (int n = 0; n < 8; n++)
            #pragma unroll
            for (int r = 0; r < 4; r++) acc[mt][n][r] = 0.f;

    loadStage(0, 0);

    for (int i = 0; i < 32; i++){
        CPWAIT(0);
        __syncthreads();
        if (i + 1 < 32) loadStage((i+1) & 1, (i+1)*64);

        const uint32_t ab = sb + (i&1)*A_ST;
        const uint32_t bb = sb + 2*A_ST + (i&1)*B_ST;
        #pragma unroll
        for (int kt = 0; kt < 4; kt++){
            uint4 af[2];
            #pragma unroll
            for (int mt = 0; mt < 2; mt++){
                int r = wm*32 + mt*16 + (lane & 15);
                int c = kt*2 + (lane >> 4);
                LDSM4(af[mt], ab + r*128 + ((c ^ (r & 7)) << 4));
            }
            #pragma unroll
            for (int p = 0; p < 4; p++){
                int r = wn*64 + p*16 + ((lane >> 4) << 3) + (lane & 7);
                int c = kt*2 + ((lane >> 3) & 1);
                uint4 bq;
                LDSM4(bq, bb + r*128 + ((c ^ (r & 7)) << 4));
                uint2 b0 = make_uint2(bq.x, bq.y);
                uint2 b1 = make_uint2(bq.z, bq.w);
                #pragma unroll
                for (int mt = 0; mt < 2; mt++){
                    mma_f16(acc[mt][2*p],   af[mt], b0);
                    mma_f16(acc[mt][2*p+1], af[mt], b1);
                }
            }
        }
    }

    // -------- epilogue --------
    const int l4 = lane >> 2;
    const int l2 = (lane & 3) * 2;
    #pragma unroll
    for (int mt = 0; mt < 2; mt++){
        #pragma unroll
        for (int n = 0; n < 8; n++){
            const int col = (MODE == 0 ? n0g : n0) + wn*64 + n*8 + l2;
            #pragma unroll
            for (int half = 0; half < 2; half++){
                const int row = m0 + wm*32 + mt*16 + l4 + half*8;
                float xr = acc[mt][n][half*2 + 0];
                float xi = acc[mt][n][half*2 + 1];
                if (MODE == 0){
                    float2 o; o.x = xr; o.y = xi;
                    *(float2*)(Cf + (size_t)row*D_MODEL + col) = o;
                } else {
                    const int b = row >> 11;
                    const int s = row & (S_LEN-1);
                    const int h = col >> 7;
                    const int d = col & (HD-1);
                    __half* op = Ch + (((size_t)(b*Hn + h))*S_LEN + s)*HD + d;
                    if (rope){
                        float cs = fcos[s*(HD/2) + (d>>1)];
                        float sn = fsin[s*(HD/2) + (d>>1)];
                        *(__half2*)op = __floats2half2_rn(xr*cs - xi*sn, xr*sn + xi*cs);
                    } else {
                        *(__half2*)op = __floats2half2_rn(xr, xi);
                    }
                }
            }
        }
    }
}

// ===== Flash attention v3: BQ=64, BKT=64, 128 thr (4 warps), 2 CTAs/SM =====
// smem: Q 16KB | K[2] 2x16KB | V[2] 2x16KB | P 8KB = 88KB
// qt reversed so the heavy causal CTAs launch in wave 1.
#define ATT_SMEM 90112

__global__ void __launch_bounds__(128, 2) attn2()
{
    extern __shared__ char sm[];
    const uint32_t sb = (uint32_t)__cvta_generic_to_shared(sm);
    const uint32_t Qb = sb;
    const uint32_t Kb0 = sb + 16384, Kb1 = sb + 32768;
    const uint32_t Vb0 = sb + 49152, Vb1 = sb + 65536;
    uint32_t* Ps = (uint32_t*)(sm + 81920);   // [4 wid][4 kt][128] words = 8KB

    const int tid = threadIdx.x, lane = tid & 31, wid = tid >> 5;
    const int bz  = blockIdx.y >> 4;
    const int hh  = blockIdx.y & 15;
    const int kvh = hh >> 2;
    const int qt  = (gridDim.x - 1) - blockIdx.x;   // heavy tiles first
    const int q0  = qt * 64;

    const __half* Qg = g_Qh + ((size_t)(bz*NH   + hh )*S_LEN + q0)*HD;
    const __half* Kg = g_Kh + ((size_t)(bz*NKVH + kvh)*S_LEN)*HD;
    const __half* Vg = g_Vh + ((size_t)(bz*NKVH + kvh)*S_LEN)*HD;

    auto loadKV = [&](int buf, int k0){
        uint32_t kb = buf ? Kb1 : Kb0;
        uint32_t vb = buf ? Vb1 : Vb0;
        #pragma unroll
        for (int i = 0; i < 8; i++){
            int idx = tid + 128*i;
            int r = idx >> 4, c = idx & 15;
            uint32_t off = r*256 + ((c ^ (r & 7)) << 4);
            CP16(kb + off, Kg + (size_t)(k0 + r)*HD + c*8);
            CP16(vb + off, Vg + (size_t)(k0 + r)*HD + c*8);
        }
        CPCOMMIT;
    };

    // group 0: Q (64 rows) + KV(0)
    #pragma unroll
    for (int i = 0; i < 8; i++){
        int idx = tid + 128*i;
        int r = idx >> 4, c = idx & 15;
        CP16(Qb + r*256 + ((c ^ (r & 7)) << 4), Qg + (size_t)r*HD + c*8);
    }
    loadKV(0, 0);

    const int nkt = qt + 1;
    const float scale = 0.08838834764831845f;   // 1/sqrt(128)
    const int qlo = q0 + wid*16 + (lane >> 2);
    const int qhi = qlo + 8;

    uint4 qf[8];
    float m0 = -1e30f, m1 = -1e30f, l0 = 0.f, l1 = 0.f;
    float o[16][4];
    #pragma unroll
    for (int nt = 0; nt < 16; nt++)
        #pragma unroll
        for (int r = 0; r < 4; r++) o[nt][r] = 0.f;

    for (int tile = 0; tile < nkt; tile++){
        if (tile + 1 < nkt) { loadKV((tile+1) & 1, (tile+1)*64); CPWAIT(1); }
        else                { CPWAIT(0); }
        __syncthreads();

        if (tile == 0){
            #pragma unroll
            for (int kt = 0; kt < 8; kt++){
                int r = wid*16 + (lane & 15);
                int c = kt*2 + (lane >> 4);
                LDSM4(qf[kt], Qb + r*256 + ((c ^ (r & 7)) << 4));
            }
        }

        const int k0 = tile * 64;
        const uint32_t kb = (tile & 1) ? Kb1 : Kb0;
        const uint32_t vb = (tile & 1) ? Vb1 : Vb0;

        // ---- S = Q K^T (16 x 64 per warp) ----
        float sacc[8][4];
        #pragma unroll
        for (int n = 0; n < 8; n++)
            #pragma unroll
            for (int r = 0; r < 4; r++) sacc[n][r] = 0.f;
        #pragma unroll
        for (int kt = 0; kt < 8; kt++){
            #pragma unroll
            for (int p = 0; p < 4; p++){
                int r = p*16 + ((lane >> 4) << 3) + (lane & 7);
                int c = kt*2 + ((lane >> 3) & 1);
                uint4 bq;
                LDSM4(bq, kb + r*256 + ((c ^ (r & 7)) << 4));
                mma_f16(sacc[2*p],   qf[kt], make_uint2(bq.x, bq.y));
                mma_f16(sacc[2*p+1], qf[kt], make_uint2(bq.z, bq.w));
            }
        }

        // ---- online softmax ----
        const bool diag = (tile == nkt - 1);
        float mx0 = -1e30f, mx1 = -1e30f;
        #pragma unroll
        for (int n = 0; n < 8; n++){
            float v0 = sacc[n][0]*scale, v1 = sacc[n][1]*scale;
            float v2 = sacc[n][2]*scale, v3 = sacc[n][3]*scale;
            if (diag){
                int c0 = k0 + n*8 + (lane & 3)*2;
                if (c0     > qlo) v0 = -1e30f;
                if (c0 + 1 > qlo) v1 = -1e30f;
                if (c0     > qhi) v2 = -1e30f;
                if (c0 + 1 > qhi) v3 = -1e30f;
            }
            sacc[n][0]=v0; sacc[n][1]=v1; sacc[n][2]=v2; sacc[n][3]=v3;
            mx0 = fmaxf(mx0, fmaxf(v0, v1));
            mx1 = fmaxf(mx1, fmaxf(v2, v3));
        }
        mx0 = fmaxf(mx0, __shfl_xor_sync(0xffffffffu, mx0, 1));
        mx0 = fmaxf(mx0, __shfl_xor_sync(0xffffffffu, mx0, 2));
        mx1 = fmaxf(mx1, __shfl_xor_sync(0xffffffffu, mx1, 1));
        mx1 = fmaxf(mx1, __shfl_xor_sync(0xffffffffu, mx1, 2));
        float nm0 = fmaxf(m0, mx0), nm1 = fmaxf(m1, mx1);
        float cr0 = __expf(m0 - nm0), cr1 = __expf(m1 - nm1);
        m0 = nm0; m1 = nm1;

        float s0 = 0.f, s1 = 0.f;
        #pragma unroll
        for (int n = 0; n < 8; n++){
            float p0 = __expf(sacc[n][0] - nm0);
            float p1 = __expf(sacc[n][1] - nm0);
            float p2 = __expf(sacc[n][2] - nm1);
            float p3 = __expf(sacc[n][3] - nm1);
            s0 += p0 + p1; s1 += p2 + p3;
            __half2 w0 = __floats2half2_rn(p0, p1);
            __half2 w1 = __floats2half2_rn(p2, p3);
            uint2 w; w.x = *(uint32_t*)&w0; w.y = *(uint32_t*)&w1;
            *(uint2*)(Ps + (wid*4 + (n>>1))*128 + (lane>>2)*16 + (lane&3)*4 + 2*(n&1)) = w;
        }
        s0 += __shfl_xor_sync(0xffffffffu, s0, 1);
        s0 += __shfl_xor_sync(0xffffffffu, s0, 2);
        s1 += __shfl_xor_sync(0xffffffffu, s1, 1);
        s1 += __shfl_xor_sync(0xffffffffu, s1, 2);
        l0 = l0*cr0 + s0;
        l1 = l1*cr1 + s1;
        #pragma unroll
        for (int nt = 0; nt < 16; nt++){
            o[nt][0] *= cr0; o[nt][1] *= cr0;
            o[nt][2] *= cr1; o[nt][3] *= cr1;
        }
        __syncwarp();

        // ---- O += P V (16 x 128 per warp) ----
        #pragma unroll
        for (int kt = 0; kt < 4; kt++){
            uint4 pf = *(const uint4*)(Ps + (wid*4 + kt)*128 + lane*4);
            #pragma unroll
            for (int p = 0; p < 8; p++){
                int r = kt*16 + ((lane >> 3) & 1)*8 + (lane & 7);
                int c = 2*p + (lane >> 4);
                uint4 bq;
                LDSM4T(bq, vb + r*256 + ((c ^ (r & 7)) << 4));
                mma_f16(o[2*p],   pf, make_uint2(bq.x, bq.y));
                mma_f16(o[2*p+1], pf, make_uint2(bq.z, bq.w));
            }
        }
        __syncthreads();
    }

    // ---- output (fp16) ----
    float inv0 = 1.f / l0, inv1 = 1.f / l1;
    const int row_lo = q0 + wid*16 + (lane >> 2);
    const int row_hi = row_lo + 8;
    __half* olo = g_Oh + ((size_t)bz*S_LEN + row_lo)*D_MODEL + hh*HD;
    __half* ohi = g_Oh + ((size_t)bz*S_LEN + row_hi)*D_MODEL + hh*HD;
    #pragma unroll
    for (int nt = 0; nt < 16; nt++){
        int d0 = nt*8 + (lane & 3)*2;
        *(__half2*)(olo + d0) = __floats2half2_rn(o[nt][0]*inv0, o[nt][1]*inv0);
        *(__half2*)(ohi + d0) = __floats2half2_rn(o[nt][2]*inv1, o[nt][3]*inv1);
    }
}

extern "C" void kernel_launch(void* const* d_in, const int* in_sizes, int n_in,
                              void* d_out, int out_size)
{
    const float* x    = (const float*)d_in[0];
    const float* fcos = (const float*)d_in[1];
    const float* fsin = (const float*)d_in[2];
    const float* wq   = (const float*)d_in[3];
    const float* wk   = (const float*)d_in[4];
    const float* wv   = (const float*)d_in[5];
    const float* wo   = (const float*)d_in[6];
    float* out = (float*)d_out;

    __half *pXh, *pWqkv, *pWoh, *pOh;
    cudaGetSymbolAddress((void**)&pXh,  g_Xh);
    cudaGetSymbolAddress((void**)&pWqkv, g_Wqkv);
    cudaGetSymbolAddress((void**)&pWoh, g_Woh);
    cudaGetSymbolAddress((void**)&pOh,  g_Oh);

    cudaFuncSetAttribute(gemm_h<3>, cudaFuncAttributeMaxDynamicSharedMemorySize, GEMM_SMEM);
    cudaFuncSetAttribute(gemm_h<0>, cudaFuncAttributeMaxDynamicSharedMemorySize, GEMM_SMEM);
    cudaFuncSetAttribute(attn2, cudaFuncAttributeMaxDynamicSharedMemorySize, ATT_SMEM);

    // single fp32 -> fp16 prepass (x, wq, wk, wv, wo)
    cvt_all<<<CVT_TOTAL4/256, 256>>>(x, wq, wk, wv, wo);

    // fused QKV projection (+rope, scatter to [b,h,s,d] fp16)
    gemm_h<3><<<dim3(3072/128, MROWS/64), 128, GEMM_SMEM>>>(pXh, pWqkv, nullptr, fcos, fsin);
    // attention -> g_Oh [b,s,h*d] fp16
    attn2<<<dim3(S_LEN/64, B_SZ*NH), 128, ATT_SMEM>>>();
    // output projection -> d_out (f32)
    gemm_h<0><<<dim3(D_MODEL/128, MROWS/64), 128, GEMM_SMEM>>>(pOh, pWoh, out, nullptr, nullptr);
}